// round 1
// baseline (speedup 1.0000x reference)
#include <cuda_runtime.h>
#include <cuda_bf16.h>
#include <math.h>

// Problem constants
#define Bc 4
#define Tc 1024
#define Mc 256
#define Cc 512
#define Hc 8
#define HDc 64
#define C3c 1536
#define BHc 32

// ---------------- scratch (device globals; no allocation allowed) ----------------
__device__ float g_qkv_x[Bc * Tc * C3c];        // (B,T,3C)
__device__ float g_qkv_y[Bc * Mc * C3c];        // (B,M,3C)
__device__ float g_catt1[BHc * Tc];             // per (b,h,t)
__device__ float g_catt2[BHc * Mc];             // per (b,h,m)
__device__ float g_catt[(long)BHc * Tc * Mc];   // (BH,T,M)
__device__ float g_x2y[(long)BHc * Tc * Mc];
__device__ float g_y2x[(long)BHc * Tc * Mc];
__device__ float g_big[(long)BHc * Tc * Tc];    // (BH,T,T) chain/satt reuse
__device__ float g_cval[Bc * Tc * Cc];
__device__ float g_sval[Bc * Tc * Cc];
__device__ float g_gs[Bc * Tc * Cc];
__device__ float g_gc[Bc * Tc * Cc];
__device__ float g_z[Bc * Tc * Cc];

// ---------------- generic dense GEMM: Out = A(Mr,K) @ W(K,N) + bias ----------------
// 64x64 tile, BK=16, 256 threads, 4x4 per thread. Mr%64==0, N%64==0, K%16==0.
__global__ void sgemm_bias(const float* __restrict__ A, const float* __restrict__ W,
                           const float* __restrict__ bias, float* __restrict__ Out,
                           int Mr, int N, int K) {
    __shared__ float As[64][17];
    __shared__ float Bs[16][68];
    const int tid = threadIdx.x;
    const int tr = tid >> 4, tc = tid & 15;
    const int row0 = blockIdx.y * 64, col0 = blockIdx.x * 64;
    float acc[4][4] = {};
    for (int k0 = 0; k0 < K; k0 += 16) {
        #pragma unroll
        for (int w = 0; w < 4; w++) {
            int li = tid + w * 256;
            int m = li >> 4, k = li & 15;
            As[m][k] = A[(long)(row0 + m) * K + k0 + k];
        }
        #pragma unroll
        for (int w = 0; w < 4; w++) {
            int li = tid + w * 256;
            int k = li >> 6, n = li & 63;
            Bs[k][n] = W[(long)(k0 + k) * N + col0 + n];
        }
        __syncthreads();
        #pragma unroll
        for (int k = 0; k < 16; k++) {
            float a[4], b[4];
            #pragma unroll
            for (int i = 0; i < 4; i++) a[i] = As[tr * 4 + i][k];
            #pragma unroll
            for (int j = 0; j < 4; j++) b[j] = Bs[k][tc * 4 + j];
            #pragma unroll
            for (int i = 0; i < 4; i++)
                #pragma unroll
                for (int j = 0; j < 4; j++) acc[i][j] += a[i] * b[j];
        }
        __syncthreads();
    }
    #pragma unroll
    for (int i = 0; i < 4; i++)
        #pragma unroll
        for (int j = 0; j < 4; j++) {
            int r = row0 + tr * 4 + i, c = col0 + tc * 4 + j;
            float v = acc[i][j];
            if (bias) v += bias[c];
            Out[(long)r * N + c] = v;
        }
}

// ---------------- batched NT GEMM: C[bh][i][j] = alpha*sum_k A[i,k]*B[j,k] (+rb+cb) ----
// per-block 64x64 tile, K stepped by 64. grid = (J/64, I/64, BH)
__global__ void gemm_nt(const float* __restrict__ A, long Abs, long Ahs, int ldA,
                        const float* __restrict__ Bp, long Bbs, long Bhs, int ldB,
                        const float* __restrict__ scaleA,   // per-h 64 floats, or null
                        const float* __restrict__ rbias,    // (BH,I) or null
                        const float* __restrict__ cbias,    // (BH,J) or null
                        float* __restrict__ Cp, int I, int J, int K,
                        float alpha, int causal) {
    const int bh = blockIdx.z, b = bh >> 3, h = bh & 7;
    const int j0 = blockIdx.x * 64, i0 = blockIdx.y * 64;
    if (causal && j0 > i0) return;   // fully masked tile
    __shared__ float As[64][65];
    __shared__ float Bs[64][65];
    const float* Ab = A + (long)b * Abs + (long)h * Ahs + (long)i0 * ldA;
    const float* Bb = Bp + (long)b * Bbs + (long)h * Bhs + (long)j0 * ldB;
    const float* sA = scaleA ? (scaleA + h * 64) : nullptr;
    const int tid = threadIdx.x, tr = tid >> 4, tc = tid & 15;
    float acc[4][4] = {};
    for (int k0 = 0; k0 < K; k0 += 64) {
        #pragma unroll
        for (int w = 0; w < 16; w++) {
            int li = tid + w * 256;
            int r = li >> 6, k = li & 63;
            float av = Ab[(long)r * ldA + k0 + k];
            if (sA) av *= sA[k0 + k];
            As[k][r] = av;
        }
        #pragma unroll
        for (int w = 0; w < 16; w++) {
            int li = tid + w * 256;
            int r = li >> 6, k = li & 63;
            Bs[k][r] = Bb[(long)r * ldB + k0 + k];
        }
        __syncthreads();
        #pragma unroll
        for (int k = 0; k < 64; k++) {
            float a[4], bb[4];
            #pragma unroll
            for (int i = 0; i < 4; i++) a[i] = As[k][tr * 4 + i];
            #pragma unroll
            for (int j = 0; j < 4; j++) bb[j] = Bs[k][tc * 4 + j];
            #pragma unroll
            for (int i = 0; i < 4; i++)
                #pragma unroll
                for (int j = 0; j < 4; j++) acc[i][j] += a[i] * bb[j];
        }
        __syncthreads();
    }
    float* Cb = Cp + (long)bh * I * J;
    const float* rb = rbias ? rbias + (long)bh * I : nullptr;
    const float* cb = cbias ? cbias + (long)bh * J : nullptr;
    #pragma unroll
    for (int i = 0; i < 4; i++)
        #pragma unroll
        for (int j = 0; j < 4; j++) {
            int ii = i0 + tr * 4 + i, jj = j0 + tc * 4 + j;
            float v = acc[i][j] * alpha;
            if (rb) v += rb[ii];
            if (cb) v += cb[jj];
            Cb[(long)ii * J + jj] = v;
        }
}

// ---------------- batched NN GEMM, J=64 fixed: C = A(I,K) @ B(K,64) -----------------
// grid = (I/64, BH)
__global__ void gemm_nn(const float* __restrict__ A, long Abs, long Ahs, int ldA,
                        const float* __restrict__ Bp, long Bbs, long Bhs, int ldB,
                        float* __restrict__ Cp, long Cbs, long Chs, int ldC,
                        int K, int accumulate) {
    const int bh = blockIdx.y, b = bh >> 3, h = bh & 7;
    const int i0 = blockIdx.x * 64;
    __shared__ float As[64][33];
    __shared__ float Bs[32][68];
    const float* Ab = A + (long)b * Abs + (long)h * Ahs + (long)i0 * ldA;
    const float* Bb = Bp + (long)b * Bbs + (long)h * Bhs;
    const int tid = threadIdx.x, tr = tid >> 4, tc = tid & 15;
    float acc[4][4] = {};
    for (int k0 = 0; k0 < K; k0 += 32) {
        #pragma unroll
        for (int w = 0; w < 8; w++) {
            int li = tid + w * 256;
            int r = li >> 5, k = li & 31;
            As[r][k] = Ab[(long)r * ldA + k0 + k];
        }
        #pragma unroll
        for (int w = 0; w < 8; w++) {
            int li = tid + w * 256;
            int k = li >> 6, j = li & 63;
            Bs[k][j] = Bb[(long)(k0 + k) * ldB + j];
        }
        __syncthreads();
        #pragma unroll
        for (int k = 0; k < 32; k++) {
            float a[4], bb[4];
            #pragma unroll
            for (int i = 0; i < 4; i++) a[i] = As[tr * 4 + i][k];
            #pragma unroll
            for (int j = 0; j < 4; j++) bb[j] = Bs[k][tc * 4 + j];
            #pragma unroll
            for (int i = 0; i < 4; i++)
                #pragma unroll
                for (int j = 0; j < 4; j++) acc[i][j] += a[i] * bb[j];
        }
        __syncthreads();
    }
    float* Cb = Cp + (long)b * Cbs + (long)h * Chs + (long)i0 * ldC;
    #pragma unroll
    for (int i = 0; i < 4; i++)
        #pragma unroll
        for (int j = 0; j < 4; j++) {
            long off = (long)(tr * 4 + i) * ldC + tc * 4 + j;
            if (accumulate) Cb[off] += acc[i][j];
            else Cb[off] = acc[i][j];
        }
}

// -------- catt1/catt2: out[bh*rows+r] = sum_d qkv[(b*rows+r)*3C + h*64 + d]*w[h*64+d]
__global__ void dotw(const float* __restrict__ qkv, const float* __restrict__ w,
                     int rows, float* __restrict__ out) {
    int gw = (blockIdx.x * blockDim.x + threadIdx.x) >> 5;
    int lane = threadIdx.x & 31;
    if (gw >= BHc * rows) return;
    int bh = gw / rows, r = gw % rows;
    int b = bh >> 3, h = bh & 7;
    const float* p = qkv + (long)(b * rows + r) * C3c + h * HDc;
    float s = p[lane] * w[h * HDc + lane] + p[lane + 32] * w[h * HDc + lane + 32];
    #pragma unroll
    for (int o = 16; o; o >>= 1) s += __shfl_xor_sync(0xffffffffu, s, o);
    if (lane == 0) out[gw] = s;
}

// -------- row softmax over M=256, one block per row --------
__global__ void softmax_row256(const float* __restrict__ in, float* __restrict__ out) {
    long row = blockIdx.x;
    int tid = threadIdx.x;
    __shared__ float sh[8];
    float v = in[row * 256 + tid];
    float m = v;
    #pragma unroll
    for (int o = 16; o; o >>= 1) m = fmaxf(m, __shfl_xor_sync(0xffffffffu, m, o));
    if ((tid & 31) == 0) sh[tid >> 5] = m;
    __syncthreads();
    float bm = sh[0];
    #pragma unroll
    for (int i = 1; i < 8; i++) bm = fmaxf(bm, sh[i]);
    __syncthreads();
    float e = expf(v - bm);
    float s = e;
    #pragma unroll
    for (int o = 16; o; o >>= 1) s += __shfl_xor_sync(0xffffffffu, s, o);
    if ((tid & 31) == 0) sh[tid >> 5] = s;
    __syncthreads();
    float bs = 0.f;
    #pragma unroll
    for (int i = 0; i < 8; i++) bs += sh[i];
    out[row * 256 + tid] = e / bs;
}

// -------- column softmax over T=1024 (axis=-2). grid (M/64, BH), 256 thr --------
__global__ void softmax_col(const float* __restrict__ in, float* __restrict__ out) {
    int bh = blockIdx.y;
    int mx = threadIdx.x & 63;
    int ty = threadIdx.x >> 6;  // 0..3
    int m = blockIdx.x * 64 + mx;
    const float* base = in + (long)bh * Tc * Mc + m;
    __shared__ float red[256];
    __shared__ float cstat[64];
    float acc = -3.4e38f;
    for (int t = ty; t < Tc; t += 4) acc = fmaxf(acc, base[(long)t * Mc]);
    red[threadIdx.x] = acc;
    __syncthreads();
    if (ty == 0)
        cstat[mx] = fmaxf(fmaxf(red[mx], red[64 + mx]), fmaxf(red[128 + mx], red[192 + mx]));
    __syncthreads();
    float cm = cstat[mx];
    __syncthreads();
    float s = 0.f;
    for (int t = ty; t < Tc; t += 4) s += expf(base[(long)t * Mc] - cm);
    red[threadIdx.x] = s;
    __syncthreads();
    if (ty == 0) cstat[mx] = red[mx] + red[64 + mx] + red[128 + mx] + red[192 + mx];
    __syncthreads();
    float inv = 1.f / cstat[mx];
    float* ob = out + (long)bh * Tc * Mc + m;
    for (int t = ty; t < Tc; t += 4) ob[(long)t * Mc] = expf(base[(long)t * Mc] - cm) * inv;
}

// -------- causal row softmax over T=1024, in-place. one block (256 thr) per row -----
__global__ void softmax_causal(float* __restrict__ buf) {
    long row = blockIdx.x;           // bh*1024 + t
    int t = (int)(row & 1023);
    float* p = buf + row * 1024;
    int tid = threadIdx.x;
    __shared__ float sh[8];
    float v[4];
    float m = -3.4e38f;
    #pragma unroll
    for (int j = 0; j < 4; j++) {
        int s = tid + j * 256;
        v[j] = (s <= t) ? p[s] : -3.4e38f;
        m = fmaxf(m, v[j]);
    }
    #pragma unroll
    for (int o = 16; o; o >>= 1) m = fmaxf(m, __shfl_xor_sync(0xffffffffu, m, o));
    if ((tid & 31) == 0) sh[tid >> 5] = m;
    __syncthreads();
    float bm = sh[0];
    #pragma unroll
    for (int i = 1; i < 8; i++) bm = fmaxf(bm, sh[i]);
    __syncthreads();
    float sum = 0.f;
    #pragma unroll
    for (int j = 0; j < 4; j++) {
        int s = tid + j * 256;
        float e = (s <= t) ? expf(v[j] - bm) : 0.f;
        v[j] = e;
        sum += e;
    }
    #pragma unroll
    for (int o = 16; o; o >>= 1) sum += __shfl_xor_sync(0xffffffffu, sum, o);
    if ((tid & 31) == 0) sh[tid >> 5] = sum;
    __syncthreads();
    float bs = 0.f;
    #pragma unroll
    for (int i = 0; i < 8; i++) bs += sh[i];
    float inv = 1.f / bs;
    #pragma unroll
    for (int j = 0; j < 4; j++) p[tid + j * 256] = v[j] * inv;
}

// -------- elementwise --------
__global__ void add_x(float* __restrict__ a, const float* __restrict__ b, int n) {
    int i = blockIdx.x * blockDim.x + threadIdx.x;
    if (i < n) a[i] += b[i];
}
__global__ void gate_combine(const float* __restrict__ gs, const float* __restrict__ gc,
                             const float* __restrict__ cval, const float* __restrict__ sval,
                             float* __restrict__ z, int n) {
    int i = blockIdx.x * blockDim.x + threadIdx.x;
    if (i < n) {
        float sg = 1.f / (1.f + expf(-gs[i]));
        float cg = 1.f / (1.f + expf(-gc[i]));
        z[i] = sg * cval[i] + cg * sval[i];
    }
}

extern "C" void kernel_launch(void* const* d_in, const int* in_sizes, int n_in,
                              void* d_out, int out_size) {
    const float* x      = (const float*)d_in[0];
    const float* y      = (const float*)d_in[1];
    // d_in[2] = attn_x_mask (causal, known statically) — unused
    const float* Wqkv_x = (const float*)d_in[3];
    const float* bqkv_x = (const float*)d_in[4];
    const float* Wqkv_y = (const float*)d_in[5];
    const float* bqkv_y = (const float*)d_in[6];
    const float* w4x    = (const float*)d_in[7];
    const float* w4y    = (const float*)d_in[8];
    const float* w4xy   = (const float*)d_in[9];
    const float* Wgs    = (const float*)d_in[10];
    const float* bgs    = (const float*)d_in[11];
    const float* Wgc    = (const float*)d_in[12];
    const float* bgc    = (const float*)d_in[13];
    const float* Wp     = (const float*)d_in[14];
    const float* bp     = (const float*)d_in[15];
    float* out = (float*)d_out;

    float *p_qkv_x, *p_qkv_y, *p_catt1, *p_catt2, *p_catt, *p_x2y, *p_y2x,
          *p_big, *p_cval, *p_sval, *p_gs, *p_gc, *p_z;
    cudaGetSymbolAddress((void**)&p_qkv_x, g_qkv_x);
    cudaGetSymbolAddress((void**)&p_qkv_y, g_qkv_y);
    cudaGetSymbolAddress((void**)&p_catt1, g_catt1);
    cudaGetSymbolAddress((void**)&p_catt2, g_catt2);
    cudaGetSymbolAddress((void**)&p_catt, g_catt);
    cudaGetSymbolAddress((void**)&p_x2y, g_x2y);
    cudaGetSymbolAddress((void**)&p_y2x, g_y2x);
    cudaGetSymbolAddress((void**)&p_big, g_big);
    cudaGetSymbolAddress((void**)&p_cval, g_cval);
    cudaGetSymbolAddress((void**)&p_sval, g_sval);
    cudaGetSymbolAddress((void**)&p_gs, g_gs);
    cudaGetSymbolAddress((void**)&p_gc, g_gc);
    cudaGetSymbolAddress((void**)&p_z, g_z);

    const float scale = 0.125f;        // 1/sqrt(64)
    const float invSqrtM = 0.0625f;    // 1/sqrt(256)

    // 1-2. QKV projections
    sgemm_bias<<<dim3(C3c / 64, (Bc * Tc) / 64), 256>>>(x, Wqkv_x, bqkv_x, p_qkv_x,
                                                        Bc * Tc, C3c, Cc);
    sgemm_bias<<<dim3(C3c / 64, (Bc * Mc) / 64), 256>>>(y, Wqkv_y, bqkv_y, p_qkv_y,
                                                        Bc * Mc, C3c, Cc);

    // 3. per-row bias terms  catt1 = q_x . w4x,  catt2 = q_y . w4y
    dotw<<<(BHc * Tc) / 8, 256>>>(p_qkv_x, w4x, Tc, p_catt1);
    dotw<<<(BHc * Mc) / 8, 256>>>(p_qkv_y, w4y, Mc, p_catt2);

    // 4. catt = scale * (q_x*w4xy) @ k_y^T + catt1 + catt2
    gemm_nt<<<dim3(Mc / 64, Tc / 64, BHc), 256>>>(
        p_qkv_x, (long)Tc * C3c, 64, C3c,
        p_qkv_y + Cc, (long)Mc * C3c, 64, C3c,
        w4xy, p_catt1, p_catt2,
        p_catt, Tc, Mc, HDc, scale, 0);

    // 5-6. softmaxes
    softmax_row256<<<BHc * Tc, 256>>>(p_catt, p_x2y);
    softmax_col<<<dim3(Mc / 64, BHc), 256>>>(p_catt, p_y2x);

    // 7. cval_x2y = x2y @ v_y  -> g_cval (=)
    gemm_nn<<<dim3(Tc / 64, BHc), 256>>>(
        p_x2y, 8L * Tc * Mc, (long)Tc * Mc, Mc,
        p_qkv_y + 2 * Cc, (long)Mc * C3c, 64, C3c,
        p_cval, (long)Tc * Cc, 64, Cc, Mc, 0);

    // 8-9. chain = softmax_causal( (1/sqrt(M)) * x2y @ y2x^T )
    gemm_nt<<<dim3(Tc / 64, Tc / 64, BHc), 256>>>(
        p_x2y, 8L * Tc * Mc, (long)Tc * Mc, Mc,
        p_y2x, 8L * Tc * Mc, (long)Tc * Mc, Mc,
        nullptr, nullptr, nullptr,
        p_big, Tc, Tc, Mc, invSqrtM, 1);
    softmax_causal<<<BHc * Tc, 256>>>(p_big);

    // 10. cval += chain @ v_x
    gemm_nn<<<dim3(Tc / 64, BHc), 256>>>(
        p_big, 8L * Tc * Tc, (long)Tc * Tc, Tc,
        p_qkv_x + 2 * Cc, (long)Tc * C3c, 64, C3c,
        p_cval, (long)Tc * Cc, 64, Cc, Tc, 1);

    // 11. cval += x
    add_x<<<(Bc * Tc * Cc) / 256, 256>>>(p_cval, x, Bc * Tc * Cc);

    // 12-14. masked self-attention: satt -> softmax -> sval
    gemm_nt<<<dim3(Tc / 64, Tc / 64, BHc), 256>>>(
        p_qkv_x, (long)Tc * C3c, 64, C3c,
        p_qkv_x + Cc, (long)Tc * C3c, 64, C3c,
        nullptr, nullptr, nullptr,
        p_big, Tc, Tc, HDc, scale, 1);
    softmax_causal<<<BHc * Tc, 256>>>(p_big);
    gemm_nn<<<dim3(Tc / 64, BHc), 256>>>(
        p_big, 8L * Tc * Tc, (long)Tc * Tc, Tc,
        p_qkv_x + 2 * Cc, (long)Tc * C3c, 64, C3c,
        p_sval, (long)Tc * Cc, 64, Cc, Tc, 0);

    // 15-16. gates
    sgemm_bias<<<dim3(Cc / 64, (Bc * Tc) / 64), 256>>>(p_sval, Wgs, bgs, p_gs,
                                                       Bc * Tc, Cc, Cc);
    sgemm_bias<<<dim3(Cc / 64, (Bc * Tc) / 64), 256>>>(p_cval, Wgc, bgc, p_gc,
                                                       Bc * Tc, Cc, Cc);

    // 17. z = sigmoid(gs)*cval + sigmoid(gc)*sval
    gate_combine<<<(Bc * Tc * Cc) / 256, 256>>>(p_gs, p_gc, p_cval, p_sval, p_z,
                                                Bc * Tc * Cc);

    // 18. out = z @ Wp + bp
    sgemm_bias<<<dim3(Cc / 64, (Bc * Tc) / 64), 256>>>(p_z, Wp, bp, out,
                                                       Bc * Tc, Cc, Cc);
}

// round 2
// speedup vs baseline: 1.7431x; 1.7431x over previous
#include <cuda_runtime.h>
#include <cuda_bf16.h>
#include <math.h>

// Problem constants
#define Bc 4
#define Tc 1024
#define Mc 256
#define Cc 512
#define Hc 8
#define HDc 64
#define C3c 1536
#define BHc 32

// ---------------- scratch (device globals) ----------------
__device__ float g_qkv_x[Bc * Tc * C3c];
__device__ float g_qkv_y[Bc * Mc * C3c];
__device__ float g_catt1[BHc * Tc];
__device__ float g_catt2[BHc * Mc];
__device__ float g_catt[(long)BHc * Tc * Mc];
__device__ float g_x2y[(long)BHc * Tc * Mc];
__device__ float g_y2x[(long)BHc * Tc * Mc];
__device__ float g_big[(long)BHc * Tc * Tc];
__device__ float g_cval[Bc * Tc * Cc];
__device__ float g_sval[Bc * Tc * Cc];
__device__ float g_gs[Bc * Tc * Cc];
__device__ float g_gc[Bc * Tc * Cc];
__device__ float g_z[Bc * Tc * Cc];

// ---------------- helpers ----------------
__device__ __forceinline__ unsigned f2tf(float f) {
    unsigned u;
    asm("cvt.rna.tf32.f32 %0, %1;" : "=r"(u) : "f"(f));
    return u;
}
__device__ __forceinline__ void mma8(float* d, const unsigned* a, const unsigned* b) {
    asm volatile(
        "mma.sync.aligned.m16n8k8.row.col.f32.tf32.tf32.f32 "
        "{%0,%1,%2,%3},{%4,%5,%6,%7},{%8,%9},{%0,%1,%2,%3};"
        : "+f"(d[0]), "+f"(d[1]), "+f"(d[2]), "+f"(d[3])
        : "r"(a[0]), "r"(a[1]), "r"(a[2]), "r"(a[3]), "r"(b[0]), "r"(b[1]));
}

// ================= NT tensor-core GEMM =================
// C[bh][i][j] = alpha * sum_k A[i,k]*B[j,k]  (+rbias[i] +cbias[j])
// CTA tile 128x128, warp tile 64x32 (2m x 4n warps), BK=32.
// grid = (J/128, I/128, BH), 256 threads.
__global__ void mma_nt(const float* __restrict__ A, long Abs, long Ahs, int ldA,
                       const float* __restrict__ Bp, long Bbs, long Bhs, int ldB,
                       const float* __restrict__ scaleA,
                       const float* __restrict__ rbias,
                       const float* __restrict__ cbias,
                       float* __restrict__ Cp, int I, int J, int K,
                       float alpha, int causal) {
    const int bh = blockIdx.z, b = bh >> 3, h = bh & 7;
    const int j0 = blockIdx.x * 128, i0 = blockIdx.y * 128;
    if (causal && j0 > i0) return;
    __shared__ unsigned As[128][36];
    __shared__ unsigned Bs[128][36];
    const float* Ab = A + (long)b * Abs + (long)h * Ahs + (long)i0 * ldA;
    const float* Bb = Bp + (long)b * Bbs + (long)h * Bhs + (long)j0 * ldB;
    const float* sA = scaleA ? (scaleA + h * HDc) : nullptr;

    const int tid = threadIdx.x;
    const int wid = tid >> 5, lane = tid & 31;
    const int g = lane >> 2, t = lane & 3;
    const int wm = (wid & 1) * 64, wn = (wid >> 1) * 32;

    float acc[4][4][4] = {};

    for (int k0 = 0; k0 < K; k0 += 32) {
        #pragma unroll
        for (int w = 0; w < 16; w++) {
            int li = tid + w * 256;
            int r = li >> 5, k = li & 31;
            float av = Ab[(long)r * ldA + k0 + k];
            if (sA) av *= sA[k0 + k];
            As[r][k] = f2tf(av);
        }
        #pragma unroll
        for (int w = 0; w < 16; w++) {
            int li = tid + w * 256;
            int r = li >> 5, k = li & 31;
            Bs[r][k] = f2tf(Bb[(long)r * ldB + k0 + k]);
        }
        __syncthreads();
        #pragma unroll
        for (int kk = 0; kk < 4; kk++) {
            const int kb = kk * 8;
            unsigned a[4][4], bb[4][2];
            #pragma unroll
            for (int mf = 0; mf < 4; mf++) {
                int row = wm + mf * 16;
                a[mf][0] = As[row + g][kb + t];
                a[mf][1] = As[row + g + 8][kb + t];
                a[mf][2] = As[row + g][kb + t + 4];
                a[mf][3] = As[row + g + 8][kb + t + 4];
            }
            #pragma unroll
            for (int nf = 0; nf < 4; nf++) {
                int col = wn + nf * 8;
                bb[nf][0] = Bs[col + g][kb + t];
                bb[nf][1] = Bs[col + g][kb + t + 4];
            }
            #pragma unroll
            for (int mf = 0; mf < 4; mf++)
                #pragma unroll
                for (int nf = 0; nf < 4; nf++) mma8(acc[mf][nf], a[mf], bb[nf]);
        }
        __syncthreads();
    }

    float* Cb = Cp + (long)bh * I * J;
    const float* rb = rbias ? rbias + (long)bh * I : nullptr;
    const float* cb = cbias ? cbias + (long)bh * J : nullptr;
    #pragma unroll
    for (int mf = 0; mf < 4; mf++)
        #pragma unroll
        for (int nf = 0; nf < 4; nf++) {
            int r0 = i0 + wm + mf * 16 + g;
            int c0 = j0 + wn + nf * 8 + 2 * t;
            #pragma unroll
            for (int e = 0; e < 4; e++) {
                int rr = r0 + (e >> 1) * 8;
                int cc = c0 + (e & 1);
                float v = acc[mf][nf][e] * alpha;
                if (rb) v += rb[rr];
                if (cb) v += cb[cc];
                Cb[(long)rr * J + cc] = v;
            }
        }
}

// ================= NN tensor-core GEMM =================
// C = A(I,K) @ B(K, J) (+bias[col]) (+=C). CTA tile 128x64, warp 64x16, BK=32.
// grid = (J/64, I/128, BH). trailK: limit K to i0+128 (lower-triangular A).
__global__ void mma_nn(const float* __restrict__ A, long Abs, long Ahs, int ldA,
                       const float* __restrict__ Bp, long Bbs, long Bhs, int ldB,
                       const float* __restrict__ bias,
                       float* __restrict__ Cp, long Cbs, long Chs, int ldC,
                       int K, int accumulate, int trailK) {
    const int bh = blockIdx.z, b = bh >> 3, h = bh & 7;
    const int col0 = blockIdx.x * 64, i0 = blockIdx.y * 128;
    __shared__ unsigned As[128][36];
    __shared__ unsigned Bs[64][36];
    const float* Ab = A + (long)b * Abs + (long)h * Ahs + (long)i0 * ldA;
    const float* Bb = Bp + (long)b * Bbs + (long)h * Bhs + col0;

    const int tid = threadIdx.x;
    const int wid = tid >> 5, lane = tid & 31;
    const int g = lane >> 2, t = lane & 3;
    const int wm = (wid & 1) * 64, wn = (wid >> 1) * 16;

    const int Keff = trailK ? min(K, i0 + 128) : K;
    float acc[4][2][4] = {};

    for (int k0 = 0; k0 < Keff; k0 += 32) {
        #pragma unroll
        for (int w = 0; w < 16; w++) {
            int li = tid + w * 256;
            int r = li >> 5, k = li & 31;
            As[r][k] = f2tf(Ab[(long)r * ldA + k0 + k]);
        }
        #pragma unroll
        for (int w = 0; w < 8; w++) {
            int li = tid + w * 256;
            int k = li >> 6, j = li & 63;
            Bs[j][k] = f2tf(Bb[(long)(k0 + k) * ldB + j]);
        }
        __syncthreads();
        #pragma unroll
        for (int kk = 0; kk < 4; kk++) {
            const int kb = kk * 8;
            unsigned a[4][4], bb[2][2];
            #pragma unroll
            for (int mf = 0; mf < 4; mf++) {
                int row = wm + mf * 16;
                a[mf][0] = As[row + g][kb + t];
                a[mf][1] = As[row + g + 8][kb + t];
                a[mf][2] = As[row + g][kb + t + 4];
                a[mf][3] = As[row + g + 8][kb + t + 4];
            }
            #pragma unroll
            for (int nf = 0; nf < 2; nf++) {
                int col = wn + nf * 8;
                bb[nf][0] = Bs[col + g][kb + t];
                bb[nf][1] = Bs[col + g][kb + t + 4];
            }
            #pragma unroll
            for (int mf = 0; mf < 4; mf++)
                #pragma unroll
                for (int nf = 0; nf < 2; nf++) mma8(acc[mf][nf], a[mf], bb[nf]);
        }
        __syncthreads();
    }

    float* Cb = Cp + (long)b * Cbs + (long)h * Chs + (long)i0 * ldC + col0;
    #pragma unroll
    for (int mf = 0; mf < 4; mf++)
        #pragma unroll
        for (int nf = 0; nf < 2; nf++) {
            int r0 = wm + mf * 16 + g;
            int c0 = wn + nf * 8 + 2 * t;
            #pragma unroll
            for (int e = 0; e < 4; e++) {
                int rr = r0 + (e >> 1) * 8;
                int cc = c0 + (e & 1);
                float v = acc[mf][nf][e];
                if (bias) v += bias[col0 + cc];
                long off = (long)rr * ldC + cc;
                if (accumulate) v += Cb[off];
                Cb[off] = v;
            }
        }
}

// -------- catt1/catt2 dot products --------
__global__ void dotw(const float* __restrict__ qkv, const float* __restrict__ w,
                     int rows, float* __restrict__ out) {
    int gw = (blockIdx.x * blockDim.x + threadIdx.x) >> 5;
    int lane = threadIdx.x & 31;
    if (gw >= BHc * rows) return;
    int bh = gw / rows, r = gw % rows;
    int b = bh >> 3, h = bh & 7;
    const float* p = qkv + (long)(b * rows + r) * C3c + h * HDc;
    float s = p[lane] * w[h * HDc + lane] + p[lane + 32] * w[h * HDc + lane + 32];
    #pragma unroll
    for (int o = 16; o; o >>= 1) s += __shfl_xor_sync(0xffffffffu, s, o);
    if (lane == 0) out[gw] = s;
}

// -------- row softmax over M=256 --------
__global__ void softmax_row256(const float* __restrict__ in, float* __restrict__ out) {
    long row = blockIdx.x;
    int tid = threadIdx.x;
    __shared__ float sh[8];
    float v = in[row * 256 + tid];
    float m = v;
    #pragma unroll
    for (int o = 16; o; o >>= 1) m = fmaxf(m, __shfl_xor_sync(0xffffffffu, m, o));
    if ((tid & 31) == 0) sh[tid >> 5] = m;
    __syncthreads();
    float bm = sh[0];
    #pragma unroll
    for (int i = 1; i < 8; i++) bm = fmaxf(bm, sh[i]);
    __syncthreads();
    float e = expf(v - bm);
    float s = e;
    #pragma unroll
    for (int o = 16; o; o >>= 1) s += __shfl_xor_sync(0xffffffffu, s, o);
    if ((tid & 31) == 0) sh[tid >> 5] = s;
    __syncthreads();
    float bs = 0.f;
    #pragma unroll
    for (int i = 0; i < 8; i++) bs += sh[i];
    out[row * 256 + tid] = e / bs;
}

// -------- column softmax over T=1024 --------
__global__ void softmax_col(const float* __restrict__ in, float* __restrict__ out) {
    int bh = blockIdx.y;
    int mx = threadIdx.x & 63;
    int ty = threadIdx.x >> 6;
    int m = blockIdx.x * 64 + mx;
    const float* base = in + (long)bh * Tc * Mc + m;
    __shared__ float red[256];
    __shared__ float cstat[64];
    float acc = -3.4e38f;
    for (int t = ty; t < Tc; t += 4) acc = fmaxf(acc, base[(long)t * Mc]);
    red[threadIdx.x] = acc;
    __syncthreads();
    if (ty == 0)
        cstat[mx] = fmaxf(fmaxf(red[mx], red[64 + mx]), fmaxf(red[128 + mx], red[192 + mx]));
    __syncthreads();
    float cm = cstat[mx];
    __syncthreads();
    float s = 0.f;
    for (int t = ty; t < Tc; t += 4) s += expf(base[(long)t * Mc] - cm);
    red[threadIdx.x] = s;
    __syncthreads();
    if (ty == 0) cstat[mx] = red[mx] + red[64 + mx] + red[128 + mx] + red[192 + mx];
    __syncthreads();
    float inv = 1.f / cstat[mx];
    float* ob = out + (long)bh * Tc * Mc + m;
    for (int t = ty; t < Tc; t += 4) ob[(long)t * Mc] = expf(base[(long)t * Mc] - cm) * inv;
}

// -------- causal row softmax over T=1024, in-place --------
__global__ void softmax_causal(float* __restrict__ buf) {
    long row = blockIdx.x;
    int t = (int)(row & 1023);
    float* p = buf + row * 1024;
    int tid = threadIdx.x;
    __shared__ float sh[8];
    float v[4];
    float m = -3.4e38f;
    #pragma unroll
    for (int j = 0; j < 4; j++) {
        int s = tid + j * 256;
        v[j] = (s <= t) ? p[s] : -3.4e38f;
        m = fmaxf(m, v[j]);
    }
    #pragma unroll
    for (int o = 16; o; o >>= 1) m = fmaxf(m, __shfl_xor_sync(0xffffffffu, m, o));
    if ((tid & 31) == 0) sh[tid >> 5] = m;
    __syncthreads();
    float bm = sh[0];
    #pragma unroll
    for (int i = 1; i < 8; i++) bm = fmaxf(bm, sh[i]);
    __syncthreads();
    float sum = 0.f;
    #pragma unroll
    for (int j = 0; j < 4; j++) {
        int s = tid + j * 256;
        float e = (s <= t) ? expf(v[j] - bm) : 0.f;
        v[j] = e;
        sum += e;
    }
    #pragma unroll
    for (int o = 16; o; o >>= 1) sum += __shfl_xor_sync(0xffffffffu, sum, o);
    if ((tid & 31) == 0) sh[tid >> 5] = sum;
    __syncthreads();
    float bs = 0.f;
    #pragma unroll
    for (int i = 0; i < 8; i++) bs += sh[i];
    float inv = 1.f / bs;
    #pragma unroll
    for (int j = 0; j < 4; j++) p[tid + j * 256] = v[j] * inv;
}

// -------- elementwise --------
__global__ void add_x(float* __restrict__ a, const float* __restrict__ b, int n) {
    int i = blockIdx.x * blockDim.x + threadIdx.x;
    if (i < n) a[i] += b[i];
}
__global__ void gate_combine(const float* __restrict__ gs, const float* __restrict__ gc,
                             const float* __restrict__ cval, const float* __restrict__ sval,
                             float* __restrict__ z, int n) {
    int i = blockIdx.x * blockDim.x + threadIdx.x;
    if (i < n) {
        float sg = 1.f / (1.f + expf(-gs[i]));
        float cg = 1.f / (1.f + expf(-gc[i]));
        z[i] = sg * cval[i] + cg * sval[i];
    }
}

extern "C" void kernel_launch(void* const* d_in, const int* in_sizes, int n_in,
                              void* d_out, int out_size) {
    const float* x      = (const float*)d_in[0];
    const float* y      = (const float*)d_in[1];
    const float* Wqkv_x = (const float*)d_in[3];
    const float* bqkv_x = (const float*)d_in[4];
    const float* Wqkv_y = (const float*)d_in[5];
    const float* bqkv_y = (const float*)d_in[6];
    const float* w4x    = (const float*)d_in[7];
    const float* w4y    = (const float*)d_in[8];
    const float* w4xy   = (const float*)d_in[9];
    const float* Wgs    = (const float*)d_in[10];
    const float* bgs    = (const float*)d_in[11];
    const float* Wgc    = (const float*)d_in[12];
    const float* bgc    = (const float*)d_in[13];
    const float* Wp     = (const float*)d_in[14];
    const float* bp     = (const float*)d_in[15];
    float* out = (float*)d_out;

    float *p_qkv_x, *p_qkv_y, *p_catt1, *p_catt2, *p_catt, *p_x2y, *p_y2x,
          *p_big, *p_cval, *p_sval, *p_gs, *p_gc, *p_z;
    cudaGetSymbolAddress((void**)&p_qkv_x, g_qkv_x);
    cudaGetSymbolAddress((void**)&p_qkv_y, g_qkv_y);
    cudaGetSymbolAddress((void**)&p_catt1, g_catt1);
    cudaGetSymbolAddress((void**)&p_catt2, g_catt2);
    cudaGetSymbolAddress((void**)&p_catt, g_catt);
    cudaGetSymbolAddress((void**)&p_x2y, g_x2y);
    cudaGetSymbolAddress((void**)&p_y2x, g_y2x);
    cudaGetSymbolAddress((void**)&p_big, g_big);
    cudaGetSymbolAddress((void**)&p_cval, g_cval);
    cudaGetSymbolAddress((void**)&p_sval, g_sval);
    cudaGetSymbolAddress((void**)&p_gs, g_gs);
    cudaGetSymbolAddress((void**)&p_gc, g_gc);
    cudaGetSymbolAddress((void**)&p_z, g_z);

    const float scale = 0.125f;
    const float invSqrtM = 0.0625f;

    // 1-2. QKV projections (dense NN)
    mma_nn<<<dim3(C3c / 64, (Bc * Tc) / 128, 1), 256>>>(
        x, 0, 0, Cc, Wqkv_x, 0, 0, C3c, bqkv_x,
        p_qkv_x, 0, 0, C3c, Cc, 0, 0);
    mma_nn<<<dim3(C3c / 64, (Bc * Mc) / 128, 1), 256>>>(
        y, 0, 0, Cc, Wqkv_y, 0, 0, C3c, bqkv_y,
        p_qkv_y, 0, 0, C3c, Cc, 0, 0);

    // 3. bias terms
    dotw<<<(BHc * Tc) / 8, 256>>>(p_qkv_x, w4x, Tc, p_catt1);
    dotw<<<(BHc * Mc) / 8, 256>>>(p_qkv_y, w4y, Mc, p_catt2);

    // 4. catt = scale * (q_x*w4xy) @ k_y^T + catt1 + catt2
    mma_nt<<<dim3(Mc / 128, Tc / 128, BHc), 256>>>(
        p_qkv_x, (long)Tc * C3c, 64, C3c,
        p_qkv_y + Cc, (long)Mc * C3c, 64, C3c,
        w4xy, p_catt1, p_catt2,
        p_catt, Tc, Mc, HDc, scale, 0);

    // 5-6. softmaxes
    softmax_row256<<<BHc * Tc, 256>>>(p_catt, p_x2y);
    softmax_col<<<dim3(Mc / 64, BHc), 256>>>(p_catt, p_y2x);

    // 7. cval_x2y = x2y @ v_y
    mma_nn<<<dim3(1, Tc / 128, BHc), 256>>>(
        p_x2y, 8L * Tc * Mc, (long)Tc * Mc, Mc,
        p_qkv_y + 2 * Cc, (long)Mc * C3c, 64, C3c, nullptr,
        p_cval, (long)Tc * Cc, 64, Cc, Mc, 0, 0);

    // 8-9. chain
    mma_nt<<<dim3(Tc / 128, Tc / 128, BHc), 256>>>(
        p_x2y, 8L * Tc * Mc, (long)Tc * Mc, Mc,
        p_y2x, 8L * Tc * Mc, (long)Tc * Mc, Mc,
        nullptr, nullptr, nullptr,
        p_big, Tc, Tc, Mc, invSqrtM, 1);
    softmax_causal<<<BHc * Tc, 256>>>(p_big);

    // 10. cval += chain @ v_x   (triangular K)
    mma_nn<<<dim3(1, Tc / 128, BHc), 256>>>(
        p_big, 8L * Tc * Tc, (long)Tc * Tc, Tc,
        p_qkv_x + 2 * Cc, (long)Tc * C3c, 64, C3c, nullptr,
        p_cval, (long)Tc * Cc, 64, Cc, Tc, 1, 1);

    // 11. cval += x
    add_x<<<(Bc * Tc * Cc) / 256, 256>>>(p_cval, x, Bc * Tc * Cc);

    // 12-14. self-attention
    mma_nt<<<dim3(Tc / 128, Tc / 128, BHc), 256>>>(
        p_qkv_x, (long)Tc * C3c, 64, C3c,
        p_qkv_x + Cc, (long)Tc * C3c, 64, C3c,
        nullptr, nullptr, nullptr,
        p_big, Tc, Tc, HDc, scale, 1);
    softmax_causal<<<BHc * Tc, 256>>>(p_big);
    mma_nn<<<dim3(1, Tc / 128, BHc), 256>>>(
        p_big, 8L * Tc * Tc, (long)Tc * Tc, Tc,
        p_qkv_x + 2 * Cc, (long)Tc * C3c, 64, C3c, nullptr,
        p_sval, (long)Tc * Cc, 64, Cc, Tc, 0, 1);

    // 15-16. gates
    mma_nn<<<dim3(Cc / 64, (Bc * Tc) / 128, 1), 256>>>(
        p_sval, 0, 0, Cc, Wgs, 0, 0, Cc, bgs,
        p_gs, 0, 0, Cc, Cc, 0, 0);
    mma_nn<<<dim3(Cc / 64, (Bc * Tc) / 128, 1), 256>>>(
        p_cval, 0, 0, Cc, Wgc, 0, 0, Cc, bgc,
        p_gc, 0, 0, Cc, Cc, 0, 0);

    // 17. combine
    gate_combine<<<(Bc * Tc * Cc) / 256, 256>>>(p_gs, p_gc, p_cval, p_sval, p_z,
                                                Bc * Tc * Cc);

    // 18. out = z @ Wp + bp
    mma_nn<<<dim3(Cc / 64, (Bc * Tc) / 128, 1), 256>>>(
        p_z, 0, 0, Cc, Wp, 0, 0, Cc, bp,
        out, 0, 0, Cc, Cc, 0, 0);
}

// round 3
// speedup vs baseline: 2.5259x; 1.4491x over previous
#include <cuda_runtime.h>
#include <cuda_bf16.h>
#include <math.h>

#define Bc 4
#define Tc 1024
#define Mc 256
#define Cc 512
#define Hc 8
#define HDc 64
#define C3c 1536
#define BHc 32

// ---------------- scratch ----------------
__device__ float g_qkv_x[Bc * Tc * C3c];
__device__ float g_qkv_y[Bc * Mc * C3c];
__device__ float g_catt1[BHc * Tc];
__device__ float g_catt2[BHc * Mc];
__device__ float g_catt[(long)BHc * Tc * Mc];
__device__ float g_x2y[(long)BHc * Tc * Mc];
__device__ float g_y2x[(long)BHc * Tc * Mc];
__device__ float g_big[(long)BHc * Tc * Tc];
__device__ float g_cval[Bc * Tc * Cc];
__device__ float g_sval[Bc * Tc * Cc];
__device__ float g_gs[Bc * Tc * Cc];
__device__ float g_gc[Bc * Tc * Cc];
__device__ float g_z[Bc * Tc * Cc];

// ---------------- helpers ----------------
__device__ __forceinline__ unsigned f2tf(float f) {
    unsigned u;
    asm("cvt.rna.tf32.f32 %0, %1;" : "=r"(u) : "f"(f));
    return u;
}
__device__ __forceinline__ void mma8(float* d, const unsigned* a, const unsigned* b) {
    asm volatile(
        "mma.sync.aligned.m16n8k8.row.col.f32.tf32.tf32.f32 "
        "{%0,%1,%2,%3},{%4,%5,%6,%7},{%8,%9},{%0,%1,%2,%3};"
        : "+f"(d[0]), "+f"(d[1]), "+f"(d[2]), "+f"(d[3])
        : "r"(a[0]), "r"(a[1]), "r"(a[2]), "r"(a[3]), "r"(b[0]), "r"(b[1]));
}
__device__ __forceinline__ void cpa16(unsigned dst, const void* src) {
    asm volatile("cp.async.cg.shared.global [%0], [%1], 16;" :: "r"(dst), "l"(src));
}
__device__ __forceinline__ void cpcommit() { asm volatile("cp.async.commit_group;"); }
__device__ __forceinline__ void ldsm4(unsigned& r0, unsigned& r1, unsigned& r2, unsigned& r3,
                                      unsigned addr) {
    asm volatile("ldmatrix.sync.aligned.m8n8.x4.shared.b16 {%0,%1,%2,%3},[%4];"
                 : "=r"(r0), "=r"(r1), "=r"(r2), "=r"(r3) : "r"(addr));
}

#define NT_STAGE (128 * 36)            // words per stage per array
#define NT_SMEM (4 * NT_STAGE * 4)     // 2 stages x 2 arrays, bytes = 73728
#define NN_ASTG (128 * 36)
#define NN_BSTG (32 * 68)
#define NN_SMEM ((2 * NN_ASTG + 2 * NN_BSTG) * 4)   // 54272

extern __shared__ unsigned smem_u[];

// ================= NT GEMM: C = alpha * A(I,K) @ B(J,K)^T (+rb +cb) =================
// CTA 128x128, warp 64x32, BK=32, 2-stage cp.async, ldmatrix fragments.
__global__ void __launch_bounds__(256, 2)
mma_nt(const float* __restrict__ A, long Abs, long Ahs, int ldA,
       const float* __restrict__ Bp, long Bbs, long Bhs, int ldB,
       const float* __restrict__ scaleA,
       const float* __restrict__ rbias, const float* __restrict__ cbias,
       float* __restrict__ Cp, int I, int J, int K, float alpha, int causal) {
    const int bh = blockIdx.z, b = bh >> 3, h = bh & 7;
    const int j0 = blockIdx.x * 128, i0 = blockIdx.y * 128;
    if (causal && j0 > i0) return;
    unsigned* As = smem_u;                 // [2][128][36]
    unsigned* Bs = smem_u + 2 * NT_STAGE;  // [2][128][36]
    const unsigned sA0 = (unsigned)__cvta_generic_to_shared(As);
    const unsigned sB0 = (unsigned)__cvta_generic_to_shared(Bs);
    const float* Ab = A + (long)b * Abs + (long)h * Ahs + (long)i0 * ldA;
    const float* Bb = Bp + (long)b * Bbs + (long)h * Bhs + (long)j0 * ldB;

    const int tid = threadIdx.x, wid = tid >> 5, lane = tid & 31;
    const int g = lane >> 2, t = lane & 3;
    const int wm = (wid & 1) * 64, wn = (wid >> 1) * 32;
    const int lrow = lane & 15, lblk = lane >> 4;
    const int ldrow = tid >> 3, ldc4 = (tid & 7) * 4;

    float sreg[16];
    const bool hasS = (scaleA != nullptr);
    if (hasS) {
        const float* sA = scaleA + h * HDc;
        #pragma unroll
        for (int j = 0; j < 8; j++) {
            sreg[2 * j] = sA[8 * j + t];
            sreg[2 * j + 1] = sA[8 * j + t + 4];
        }
    }

    const int niter = K / 32;
    float acc[4][4][4] = {};

    // prologue: stage 0
    {
        const int k0 = 0;
        #pragma unroll
        for (int w = 0; w < 4; w++) {
            int r = ldrow + w * 32;
            cpa16(sA0 + (r * 36 + ldc4) * 4, Ab + (long)r * ldA + k0 + ldc4);
            cpa16(sB0 + (r * 36 + ldc4) * 4, Bb + (long)r * ldB + k0 + ldc4);
        }
        cpcommit();
    }

    for (int it = 0; it < niter; it++) {
        if (it + 1 < niter) {
            const int k0 = (it + 1) * 32, buf = (it + 1) & 1;
            #pragma unroll
            for (int w = 0; w < 4; w++) {
                int r = ldrow + w * 32;
                cpa16(sA0 + (buf * NT_STAGE + r * 36 + ldc4) * 4,
                      Ab + (long)r * ldA + k0 + ldc4);
                cpa16(sB0 + (buf * NT_STAGE + r * 36 + ldc4) * 4,
                      Bb + (long)r * ldB + k0 + ldc4);
            }
            cpcommit();
            asm volatile("cp.async.wait_group 1;");
        } else {
            asm volatile("cp.async.wait_group 0;");
        }
        __syncthreads();

        const int buf = it & 1;
        const unsigned aBase = sA0 + buf * NT_STAGE * 4;
        const unsigned bBase = sB0 + buf * NT_STAGE * 4;
        #pragma unroll
        for (int kk = 0; kk < 4; kk++) {
            const int kb = kk * 8 + 4 * lblk;
            unsigned a[4][4], bb[4][2];
            #pragma unroll
            for (int mf = 0; mf < 4; mf++)
                ldsm4(a[mf][0], a[mf][1], a[mf][2], a[mf][3],
                      aBase + ((wm + mf * 16 + lrow) * 36 + kb) * 4);
            #pragma unroll
            for (int p = 0; p < 2; p++) {
                unsigned r0, r1, r2, r3;
                ldsm4(r0, r1, r2, r3, bBase + ((wn + p * 16 + lrow) * 36 + kb) * 4);
                bb[2 * p][0] = f2tf(__uint_as_float(r0));
                bb[2 * p][1] = f2tf(__uint_as_float(r2));
                bb[2 * p + 1][0] = f2tf(__uint_as_float(r1));
                bb[2 * p + 1][1] = f2tf(__uint_as_float(r3));
            }
            if (hasS) {
                const int j = it * 4 + kk;
                const float slo = sreg[2 * j], shi = sreg[2 * j + 1];
                #pragma unroll
                for (int mf = 0; mf < 4; mf++) {
                    a[mf][0] = f2tf(__uint_as_float(a[mf][0]) * slo);
                    a[mf][1] = f2tf(__uint_as_float(a[mf][1]) * slo);
                    a[mf][2] = f2tf(__uint_as_float(a[mf][2]) * shi);
                    a[mf][3] = f2tf(__uint_as_float(a[mf][3]) * shi);
                }
            } else {
                #pragma unroll
                for (int mf = 0; mf < 4; mf++)
                    #pragma unroll
                    for (int q = 0; q < 4; q++)
                        a[mf][q] = f2tf(__uint_as_float(a[mf][q]));
            }
            #pragma unroll
            for (int mf = 0; mf < 4; mf++)
                #pragma unroll
                for (int nf = 0; nf < 4; nf++) mma8(acc[mf][nf], a[mf], bb[nf]);
        }
        __syncthreads();
    }

    float* Cb = Cp + (long)bh * I * J;
    const float* rb = rbias ? rbias + (long)bh * I : nullptr;
    const float* cb = cbias ? cbias + (long)bh * J : nullptr;
    #pragma unroll
    for (int mf = 0; mf < 4; mf++)
        #pragma unroll
        for (int nf = 0; nf < 4; nf++) {
            int r0 = i0 + wm + mf * 16 + g;
            int c0 = j0 + wn + nf * 8 + 2 * t;
            #pragma unroll
            for (int ep = 0; ep < 2; ep++) {
                int rr = r0 + ep * 8;
                float v0 = acc[mf][nf][2 * ep] * alpha;
                float v1 = acc[mf][nf][2 * ep + 1] * alpha;
                if (rb) { v0 += rb[rr]; v1 += rb[rr]; }
                if (cb) { v0 += cb[c0]; v1 += cb[c0 + 1]; }
                *(float2*)&Cb[(long)rr * J + c0] = make_float2(v0, v1);
            }
        }
}

// ================= NN GEMM: C = A(I,K) @ B(K,J-tile 64) (+bias) (+=) =================
// CTA 128x64, warp 64x16, BK=32, 2-stage cp.async; A via ldmatrix, B scalar LDS.
__global__ void __launch_bounds__(256, 2)
mma_nn(const float* __restrict__ A, long Abs, long Ahs, int ldA,
       const float* __restrict__ Bp, long Bbs, long Bhs, int ldB,
       const float* __restrict__ bias,
       float* __restrict__ Cp, long Cbs, long Chs, int ldC,
       int K, int accumulate, int trailK) {
    const int bh = blockIdx.z, b = bh >> 3, h = bh & 7;
    const int col0 = blockIdx.x * 64, i0 = blockIdx.y * 128;
    unsigned* As = smem_u;                 // [2][128][36]
    unsigned* Bs = smem_u + 2 * NN_ASTG;   // [2][32][68]
    const unsigned sA0 = (unsigned)__cvta_generic_to_shared(As);
    const unsigned sB0 = (unsigned)__cvta_generic_to_shared(Bs);
    const float* Ab = A + (long)b * Abs + (long)h * Ahs + (long)i0 * ldA;
    const float* Bb = Bp + (long)b * Bbs + (long)h * Bhs + col0;

    const int tid = threadIdx.x, wid = tid >> 5, lane = tid & 31;
    const int g = lane >> 2, t = lane & 3;
    const int wm = (wid & 1) * 64, wn = (wid >> 1) * 16;
    const int lrow = lane & 15, lblk = lane >> 4;
    const int ldrow = tid >> 3, ldc4 = (tid & 7) * 4;

    const int Keff = trailK ? min(K, i0 + 128) : K;
    const int niter = Keff / 32;
    float acc[4][2][4] = {};

    // prologue
    {
        const int k0 = 0;
        #pragma unroll
        for (int w = 0; w < 4; w++) {
            int r = ldrow + w * 32;
            cpa16(sA0 + (r * 36 + ldc4) * 4, Ab + (long)r * ldA + k0 + ldc4);
        }
        #pragma unroll
        for (int w = 0; w < 2; w++) {
            int li = tid + w * 256;
            int r = li >> 4, c4 = (li & 15) * 4;
            cpa16(sB0 + (r * 68 + c4) * 4, Bb + (long)(k0 + r) * ldB + c4);
        }
        cpcommit();
    }

    for (int it = 0; it < niter; it++) {
        if (it + 1 < niter) {
            const int k0 = (it + 1) * 32, buf = (it + 1) & 1;
            #pragma unroll
            for (int w = 0; w < 4; w++) {
                int r = ldrow + w * 32;
                cpa16(sA0 + (buf * NN_ASTG + r * 36 + ldc4) * 4,
                      Ab + (long)r * ldA + k0 + ldc4);
            }
            #pragma unroll
            for (int w = 0; w < 2; w++) {
                int li = tid + w * 256;
                int r = li >> 4, c4 = (li & 15) * 4;
                cpa16(sB0 + (buf * NN_BSTG + r * 68 + c4) * 4,
                      Bb + (long)(k0 + r) * ldB + c4);
            }
            cpcommit();
            asm volatile("cp.async.wait_group 1;");
        } else {
            asm volatile("cp.async.wait_group 0;");
        }
        __syncthreads();

        const int buf = it & 1;
        const unsigned aBase = sA0 + buf * NN_ASTG * 4;
        const unsigned* Bbuf = Bs + buf * NN_BSTG;
        #pragma unroll
        for (int kk = 0; kk < 4; kk++) {
            const int kb8 = kk * 8;
            unsigned a[4][4], bb[2][2];
            #pragma unroll
            for (int mf = 0; mf < 4; mf++) {
                ldsm4(a[mf][0], a[mf][1], a[mf][2], a[mf][3],
                      aBase + ((wm + mf * 16 + lrow) * 36 + kb8 + 4 * lblk) * 4);
                #pragma unroll
                for (int q = 0; q < 4; q++)
                    a[mf][q] = f2tf(__uint_as_float(a[mf][q]));
            }
            #pragma unroll
            for (int nf = 0; nf < 2; nf++) {
                bb[nf][0] = f2tf(__uint_as_float(Bbuf[(kb8 + t) * 68 + wn + nf * 8 + g]));
                bb[nf][1] = f2tf(__uint_as_float(Bbuf[(kb8 + t + 4) * 68 + wn + nf * 8 + g]));
            }
            #pragma unroll
            for (int mf = 0; mf < 4; mf++)
                #pragma unroll
                for (int nf = 0; nf < 2; nf++) mma8(acc[mf][nf], a[mf], bb[nf]);
        }
        __syncthreads();
    }

    float* Cb = Cp + (long)b * Cbs + (long)h * Chs + (long)i0 * ldC + col0;
    #pragma unroll
    for (int mf = 0; mf < 4; mf++)
        #pragma unroll
        for (int nf = 0; nf < 2; nf++) {
            int r0 = wm + mf * 16 + g;
            int c0 = wn + nf * 8 + 2 * t;
            #pragma unroll
            for (int e = 0; e < 4; e++) {
                int rr = r0 + (e >> 1) * 8;
                int cc = c0 + (e & 1);
                float v = acc[mf][nf][e];
                if (bias) v += bias[col0 + cc];
                long off = (long)rr * ldC + cc;
                if (accumulate) v += Cb[off];
                Cb[off] = v;
            }
        }
}

// -------- catt1/catt2 dot products --------
__global__ void dotw(const float* __restrict__ qkv, const float* __restrict__ w,
                     int rows, float* __restrict__ out) {
    int gw = (blockIdx.x * blockDim.x + threadIdx.x) >> 5;
    int lane = threadIdx.x & 31;
    if (gw >= BHc * rows) return;
    int bh = gw / rows, r = gw % rows;
    int b = bh >> 3, h = bh & 7;
    const float* p = qkv + (long)(b * rows + r) * C3c + h * HDc;
    float s = p[lane] * w[h * HDc + lane] + p[lane + 32] * w[h * HDc + lane + 32];
    #pragma unroll
    for (int o = 16; o; o >>= 1) s += __shfl_xor_sync(0xffffffffu, s, o);
    if (lane == 0) out[gw] = s;
}

// -------- row softmax over M=256 --------
__global__ void softmax_row256(const float* __restrict__ in, float* __restrict__ out) {
    long row = blockIdx.x;
    int tid = threadIdx.x;
    __shared__ float sh[8];
    float v = in[row * 256 + tid];
    float m = v;
    #pragma unroll
    for (int o = 16; o; o >>= 1) m = fmaxf(m, __shfl_xor_sync(0xffffffffu, m, o));
    if ((tid & 31) == 0) sh[tid >> 5] = m;
    __syncthreads();
    float bm = sh[0];
    #pragma unroll
    for (int i = 1; i < 8; i++) bm = fmaxf(bm, sh[i]);
    __syncthreads();
    float e = expf(v - bm);
    float s = e;
    #pragma unroll
    for (int o = 16; o; o >>= 1) s += __shfl_xor_sync(0xffffffffu, s, o);
    if ((tid & 31) == 0) sh[tid >> 5] = s;
    __syncthreads();
    float bs = 0.f;
    #pragma unroll
    for (int i = 0; i < 8; i++) bs += sh[i];
    out[row * 256 + tid] = e / bs;
}

// -------- column softmax over T=1024 --------
__global__ void softmax_col(const float* __restrict__ in, float* __restrict__ out) {
    int bh = blockIdx.y;
    int mx = threadIdx.x & 63;
    int ty = threadIdx.x >> 6;
    int m = blockIdx.x * 64 + mx;
    const float* base = in + (long)bh * Tc * Mc + m;
    __shared__ float red[256];
    __shared__ float cstat[64];
    float acc = -3.4e38f;
    for (int t = ty; t < Tc; t += 4) acc = fmaxf(acc, base[(long)t * Mc]);
    red[threadIdx.x] = acc;
    __syncthreads();
    if (ty == 0)
        cstat[mx] = fmaxf(fmaxf(red[mx], red[64 + mx]), fmaxf(red[128 + mx], red[192 + mx]));
    __syncthreads();
    float cm = cstat[mx];
    __syncthreads();
    float s = 0.f;
    for (int t = ty; t < Tc; t += 4) s += expf(base[(long)t * Mc] - cm);
    red[threadIdx.x] = s;
    __syncthreads();
    if (ty == 0) cstat[mx] = red[mx] + red[64 + mx] + red[128 + mx] + red[192 + mx];
    __syncthreads();
    float inv = 1.f / cstat[mx];
    float* ob = out + (long)bh * Tc * Mc + m;
    for (int t = ty; t < Tc; t += 4) ob[(long)t * Mc] = expf(base[(long)t * Mc] - cm) * inv;
}

// -------- causal row softmax over T=1024, in-place --------
__global__ void softmax_causal(float* __restrict__ buf) {
    long row = blockIdx.x;
    int t = (int)(row & 1023);
    float* p = buf + row * 1024;
    int tid = threadIdx.x;
    __shared__ float sh[8];
    float v[4];
    float m = -3.4e38f;
    #pragma unroll
    for (int j = 0; j < 4; j++) {
        int s = tid + j * 256;
        v[j] = (s <= t) ? p[s] : -3.4e38f;
        m = fmaxf(m, v[j]);
    }
    #pragma unroll
    for (int o = 16; o; o >>= 1) m = fmaxf(m, __shfl_xor_sync(0xffffffffu, m, o));
    if ((tid & 31) == 0) sh[tid >> 5] = m;
    __syncthreads();
    float bm = sh[0];
    #pragma unroll
    for (int i = 1; i < 8; i++) bm = fmaxf(bm, sh[i]);
    __syncthreads();
    float sum = 0.f;
    #pragma unroll
    for (int j = 0; j < 4; j++) {
        int s = tid + j * 256;
        float e = (s <= t) ? expf(v[j] - bm) : 0.f;
        v[j] = e;
        sum += e;
    }
    #pragma unroll
    for (int o = 16; o; o >>= 1) sum += __shfl_xor_sync(0xffffffffu, sum, o);
    if ((tid & 31) == 0) sh[tid >> 5] = sum;
    __syncthreads();
    float bs = 0.f;
    #pragma unroll
    for (int i = 0; i < 8; i++) bs += sh[i];
    float inv = 1.f / bs;
    #pragma unroll
    for (int j = 0; j < 4; j++) p[tid + j * 256] = v[j] * inv;
}

// -------- elementwise --------
__global__ void add_x(float* __restrict__ a, const float* __restrict__ b, int n) {
    int i = blockIdx.x * blockDim.x + threadIdx.x;
    if (i < n) a[i] += b[i];
}
__global__ void gate_combine(const float* __restrict__ gs, const float* __restrict__ gc,
                             const float* __restrict__ cval, const float* __restrict__ sval,
                             float* __restrict__ z, int n) {
    int i = blockIdx.x * blockDim.x + threadIdx.x;
    if (i < n) {
        float sg = 1.f / (1.f + expf(-gs[i]));
        float cg = 1.f / (1.f + expf(-gc[i]));
        z[i] = sg * cval[i] + cg * sval[i];
    }
}

extern "C" void kernel_launch(void* const* d_in, const int* in_sizes, int n_in,
                              void* d_out, int out_size) {
    const float* x      = (const float*)d_in[0];
    const float* y      = (const float*)d_in[1];
    const float* Wqkv_x = (const float*)d_in[3];
    const float* bqkv_x = (const float*)d_in[4];
    const float* Wqkv_y = (const float*)d_in[5];
    const float* bqkv_y = (const float*)d_in[6];
    const float* w4x    = (const float*)d_in[7];
    const float* w4y    = (const float*)d_in[8];
    const float* w4xy   = (const float*)d_in[9];
    const float* Wgs    = (const float*)d_in[10];
    const float* bgs    = (const float*)d_in[11];
    const float* Wgc    = (const float*)d_in[12];
    const float* bgc    = (const float*)d_in[13];
    const float* Wp     = (const float*)d_in[14];
    const float* bp     = (const float*)d_in[15];
    float* out = (float*)d_out;

    cudaFuncSetAttribute(mma_nt, cudaFuncAttributeMaxDynamicSharedMemorySize, NT_SMEM);
    cudaFuncSetAttribute(mma_nn, cudaFuncAttributeMaxDynamicSharedMemorySize, NN_SMEM);

    float *p_qkv_x, *p_qkv_y, *p_catt1, *p_catt2, *p_catt, *p_x2y, *p_y2x,
          *p_big, *p_cval, *p_sval, *p_gs, *p_gc, *p_z;
    cudaGetSymbolAddress((void**)&p_qkv_x, g_qkv_x);
    cudaGetSymbolAddress((void**)&p_qkv_y, g_qkv_y);
    cudaGetSymbolAddress((void**)&p_catt1, g_catt1);
    cudaGetSymbolAddress((void**)&p_catt2, g_catt2);
    cudaGetSymbolAddress((void**)&p_catt, g_catt);
    cudaGetSymbolAddress((void**)&p_x2y, g_x2y);
    cudaGetSymbolAddress((void**)&p_y2x, g_y2x);
    cudaGetSymbolAddress((void**)&p_big, g_big);
    cudaGetSymbolAddress((void**)&p_cval, g_cval);
    cudaGetSymbolAddress((void**)&p_sval, g_sval);
    cudaGetSymbolAddress((void**)&p_gs, g_gs);
    cudaGetSymbolAddress((void**)&p_gc, g_gc);
    cudaGetSymbolAddress((void**)&p_z, g_z);

    const float scale = 0.125f;
    const float invSqrtM = 0.0625f;

    // 1-2. QKV projections
    mma_nn<<<dim3(C3c / 64, (Bc * Tc) / 128, 1), 256, NN_SMEM>>>(
        x, 0, 0, Cc, Wqkv_x, 0, 0, C3c, bqkv_x,
        p_qkv_x, 0, 0, C3c, Cc, 0, 0);
    mma_nn<<<dim3(C3c / 64, (Bc * Mc) / 128, 1), 256, NN_SMEM>>>(
        y, 0, 0, Cc, Wqkv_y, 0, 0, C3c, bqkv_y,
        p_qkv_y, 0, 0, C3c, Cc, 0, 0);

    // 3. bias terms
    dotw<<<(BHc * Tc) / 8, 256>>>(p_qkv_x, w4x, Tc, p_catt1);
    dotw<<<(BHc * Mc) / 8, 256>>>(p_qkv_y, w4y, Mc, p_catt2);

    // 4. catt
    mma_nt<<<dim3(Mc / 128, Tc / 128, BHc), 256, NT_SMEM>>>(
        p_qkv_x, (long)Tc * C3c, 64, C3c,
        p_qkv_y + Cc, (long)Mc * C3c, 64, C3c,
        w4xy, p_catt1, p_catt2,
        p_catt, Tc, Mc, HDc, scale, 0);

    // 5-6. softmaxes
    softmax_row256<<<BHc * Tc, 256>>>(p_catt, p_x2y);
    softmax_col<<<dim3(Mc / 64, BHc), 256>>>(p_catt, p_y2x);

    // 7. cval_x2y = x2y @ v_y
    mma_nn<<<dim3(1, Tc / 128, BHc), 256, NN_SMEM>>>(
        p_x2y, 8L * Tc * Mc, (long)Tc * Mc, Mc,
        p_qkv_y + 2 * Cc, (long)Mc * C3c, 64, C3c, nullptr,
        p_cval, (long)Tc * Cc, 64, Cc, Mc, 0, 0);

    // 8-9. chain
    mma_nt<<<dim3(Tc / 128, Tc / 128, BHc), 256, NT_SMEM>>>(
        p_x2y, 8L * Tc * Mc, (long)Tc * Mc, Mc,
        p_y2x, 8L * Tc * Mc, (long)Tc * Mc, Mc,
        nullptr, nullptr, nullptr,
        p_big, Tc, Tc, Mc, invSqrtM, 1);
    softmax_causal<<<BHc * Tc, 256>>>(p_big);

    // 10. cval += chain @ v_x (triangular K)
    mma_nn<<<dim3(1, Tc / 128, BHc), 256, NN_SMEM>>>(
        p_big, 8L * Tc * Tc, (long)Tc * Tc, Tc,
        p_qkv_x + 2 * Cc, (long)Tc * C3c, 64, C3c, nullptr,
        p_cval, (long)Tc * Cc, 64, Cc, Tc, 1, 1);

    // 11. cval += x
    add_x<<<(Bc * Tc * Cc) / 256, 256>>>(p_cval, x, Bc * Tc * Cc);

    // 12-14. self-attention
    mma_nt<<<dim3(Tc / 128, Tc / 128, BHc), 256, NT_SMEM>>>(
        p_qkv_x, (long)Tc * C3c, 64, C3c,
        p_qkv_x + Cc, (long)Tc * C3c, 64, C3c,
        nullptr, nullptr, nullptr,
        p_big, Tc, Tc, HDc, scale, 1);
    softmax_causal<<<BHc * Tc, 256>>>(p_big);
    mma_nn<<<dim3(1, Tc / 128, BHc), 256, NN_SMEM>>>(
        p_big, 8L * Tc * Tc, (long)Tc * Tc, Tc,
        p_qkv_x + 2 * Cc, (long)Tc * C3c, 64, C3c, nullptr,
        p_sval, (long)Tc * Cc, 64, Cc, Tc, 0, 1);

    // 15-16. gates
    mma_nn<<<dim3(Cc / 64, (Bc * Tc) / 128, 1), 256, NN_SMEM>>>(
        p_sval, 0, 0, Cc, Wgs, 0, 0, Cc, bgs,
        p_gs, 0, 0, Cc, Cc, 0, 0);
    mma_nn<<<dim3(Cc / 64, (Bc * Tc) / 128, 1), 256, NN_SMEM>>>(
        p_cval, 0, 0, Cc, Wgc, 0, 0, Cc, bgc,
        p_gc, 0, 0, Cc, Cc, 0, 0);

    // 17. combine
    gate_combine<<<(Bc * Tc * Cc) / 256, 256>>>(p_gs, p_gc, p_cval, p_sval, p_z,
                                                Bc * Tc * Cc);

    // 18. out
    mma_nn<<<dim3(Cc / 64, (Bc * Tc) / 128, 1), 256, NN_SMEM>>>(
        p_z, 0, 0, Cc, Wp, 0, 0, Cc, bp,
        out, 0, 0, Cc, Cc, 0, 0);
}